// round 5
// baseline (speedup 1.0000x reference)
#include <cuda_runtime.h>

// Problem constants (fixed by the reference): B=4, S=2048, E=16, H=4, D_K=4
#define BB 4
#define SS 2048
#define EE 16
#define HH 4
#define DK 4
#define NBH (BB*HH)

#define KSPLIT 8
#define KT (SS/KSPLIT)       // 256 keys per split tile
#define THREADS 128
#define QPT 2                // queries per thread
#define QBLK (THREADS*QPT)   // 256 queries per CTA
#define PSTRIDE (BB*SS*HH)   // partial-array stride per split

typedef unsigned long long u64;

// Scratch (allocation-free rule: __device__ globals)
__device__ float g_parta[KSPLIT * BB * SS * EE];   // partial unnormalized attn out
__device__ float g_partl[KSPLIT * BB * SS * HH];   // partial softmax denominators

__device__ __forceinline__ float ex2f(float x) {
    float y; asm("ex2.approx.ftz.f32 %0, %1;" : "=f"(y) : "f"(x)); return y;
}
__device__ __forceinline__ u64 pk2(float lo, float hi) {
    u64 r; asm("mov.b64 %0, {%1, %2};" : "=l"(r) : "f"(lo), "f"(hi)); return r;
}
__device__ __forceinline__ void upk2(u64 v, float& lo, float& hi) {
    asm("mov.b64 {%0, %1}, %2;" : "=f"(lo), "=f"(hi) : "l"(v));
}
__device__ __forceinline__ u64 fma2(u64 a, u64 b, u64 c) {
    u64 d; asm("fma.rn.f32x2 %0, %1, %2, %3;" : "=l"(d) : "l"(a), "l"(b), "l"(c)); return d;
}
__device__ __forceinline__ u64 mul2(u64 a, u64 b) {
    u64 d; asm("mul.rn.f32x2 %0, %1, %2;" : "=l"(d) : "l"(a), "l"(b)); return d;
}
__device__ __forceinline__ u64 add2(u64 a, u64 b) {
    u64 d; asm("add.rn.f32x2 %0, %1, %2;" : "=l"(d) : "l"(a), "l"(b)); return d;
}

// ---------------------------------------------------------------------------
// Fused kernel: per-CTA K/V projection of its key tile + attention partials.
// K/V stored key-pair packed: u64 = (val[key 2j], val[key 2j+1]) for each d.
// Scores bounded (|s_log2| < ~12) -> no max subtraction; partials combine by
// plain addition across key splits.
// ---------------------------------------------------------------------------
__global__ void __launch_bounds__(THREADS)
attn_kernel(const float* __restrict__ x,
            const float* __restrict__ theta,
            const float* __restrict__ Wk,
            const float* __restrict__ Wv) {
    __shared__ ulonglong2 Ka[KT/2];      // (d0 pair, d1 pair) per key-pair
    __shared__ ulonglong2 Kb[KT/2];      // (d2 pair, d3 pair)
    __shared__ ulonglong2 Va[KT/2];
    __shared__ ulonglong2 Vb[KT/2];
    __shared__ float wk[DK * EE];
    __shared__ float wv[DK * EE];

    int tid = threadIdx.x;               // 0..127
    int qb  = blockIdx.x;                // 0..7
    int bh  = blockIdx.y;                // 0..15
    int ks  = blockIdx.z;                // 0..7
    int b = bh >> 2, h = bh & 3;

    if (tid < DK * EE) {
        wk[tid] = Wk[h * DK * EE + tid];
        wv[tid] = Wv[h * DK * EE + tid];
    }
    __syncthreads();

    // ---- K/V tile: thread tid computes key tokens (2*tid, 2*tid+1) ----
    {
        float kk[2][DK], vv[2][DK];
        #pragma unroll
        for (int t = 0; t < 2; t++) {
            int tok = 2 * tid + t;
            const float4* x4 = reinterpret_cast<const float4*>(
                x + ((b * SS + ks * KT) + tok) * EE);
            float xr[EE];
            #pragma unroll
            for (int r = 0; r < 4; r++) {
                float4 q = x4[r];
                xr[4*r+0] = q.x; xr[4*r+1] = q.y; xr[4*r+2] = q.z; xr[4*r+3] = q.w;
            }
            #pragma unroll
            for (int d = 0; d < DK; d++) {
                float a = 0.f, c = 0.f;
                #pragma unroll
                for (int e = 0; e < EE; e++) {
                    a = fmaf(xr[e], wk[d * EE + e], a);
                    c = fmaf(xr[e], wv[d * EE + e], c);
                }
                kk[t][d] = a; vv[t][d] = c;
            }
        }
        ulonglong2 t0, t1;
        t0.x = pk2(kk[0][0], kk[1][0]); t0.y = pk2(kk[0][1], kk[1][1]);
        t1.x = pk2(kk[0][2], kk[1][2]); t1.y = pk2(kk[0][3], kk[1][3]);
        Ka[tid] = t0; Kb[tid] = t1;
        t0.x = pk2(vv[0][0], vv[1][0]); t0.y = pk2(vv[0][1], vv[1][1]);
        t1.x = pk2(vv[0][2], vv[1][2]); t1.y = pk2(vv[0][3], vv[1][3]);
        Va[tid] = t0; Vb[tid] = t1;
    }

    // ---- queries: q = cos(x+theta) * (0.5*log2 e), duplicated-packed ----
    const float4 thv = *reinterpret_cast<const float4*>(theta + h * DK);
    const float SCL = 0.72134752044448170368f;   // 0.5 * log2(e)
    u64 qd0[QPT], qd1[QPT], qd2[QPT], qd3[QPT];
    int sq0 = qb * QBLK + tid;
    #pragma unroll
    for (int qi = 0; qi < QPT; qi++) {
        int sq = sq0 + qi * THREADS;
        const float4 xq = *reinterpret_cast<const float4*>(
            x + (b * SS + sq) * EE + h * DK);
        float q0 = cosf(xq.x + thv.x) * SCL;
        float q1 = cosf(xq.y + thv.y) * SCL;
        float q2 = cosf(xq.z + thv.z) * SCL;
        float q3 = cosf(xq.w + thv.w) * SCL;
        qd0[qi] = pk2(q0, q0); qd1[qi] = pk2(q1, q1);
        qd2[qi] = pk2(q2, q2); qd3[qi] = pk2(q3, q3);
    }

    __syncthreads();

    u64 A0[QPT], A1[QPT], A2[QPT], A3[QPT], L[QPT];
    #pragma unroll
    for (int qi = 0; qi < QPT; qi++) {
        A0[qi] = 0ULL; A1[qi] = 0ULL; A2[qi] = 0ULL; A3[qi] = 0ULL; L[qi] = 0ULL;
    }

    #pragma unroll 4
    for (int jp = 0; jp < KT/2; jp++) {
        ulonglong2 ka = Ka[jp];              // broadcast LDS.128
        ulonglong2 kb = Kb[jp];
        ulonglong2 va = Va[jp];
        ulonglong2 vb = Vb[jp];
        #pragma unroll
        for (int qi = 0; qi < QPT; qi++) {
            u64 s = mul2(qd0[qi], ka.x);
            s = fma2(qd1[qi], ka.y, s);
            s = fma2(qd2[qi], kb.x, s);
            s = fma2(qd3[qi], kb.y, s);       // s = (score_even, score_odd)
            float se, so; upk2(s, se, so);
            u64 pp = pk2(ex2f(se), ex2f(so));
            L[qi]  = add2(L[qi], pp);
            A0[qi] = fma2(pp, va.x, A0[qi]);
            A1[qi] = fma2(pp, va.y, A1[qi]);
            A2[qi] = fma2(pp, vb.x, A2[qi]);
            A3[qi] = fma2(pp, vb.y, A3[qi]);
        }
    }

    int base = ks * PSTRIDE;
    #pragma unroll
    for (int qi = 0; qi < QPT; qi++) {
        int sq = sq0 + qi * THREADS;
        int idx = base + (b * SS + sq) * HH + h;
        float e0, o0, e1, o1, e2, o2, e3, o3, le, lo;
        upk2(A0[qi], e0, o0); upk2(A1[qi], e1, o1);
        upk2(A2[qi], e2, o2); upk2(A3[qi], e3, o3);
        upk2(L[qi], le, lo);
        reinterpret_cast<float4*>(g_parta)[idx] =
            make_float4(e0 + o0, e1 + o1, e2 + o2, e3 + o3);
        g_partl[idx] = le + lo;
    }
}

// ---------------------------------------------------------------------------
// Epilogue: combine KSPLIT partials + normalize (per token-head), then
// out = att @ Wc^T (per token-quarter). Loads explicitly batched for MLP.
// ---------------------------------------------------------------------------
#define TPB 32          // tokens per block
#define ATT_PITCH 17    // padded row to avoid smem bank conflicts

__global__ void __launch_bounds__(128)
epi_kernel(const float* __restrict__ Wc, float* __restrict__ out) {
    __shared__ float wc[EE * EE];
    __shared__ float att[TPB * ATT_PITCH];

    int tid = threadIdx.x;               // 0..127
    wc[tid] = Wc[tid];
    wc[tid + 128] = Wc[tid + 128];

    int token0 = blockIdx.x * TPB;
    int tl = tid >> 2;                   // local token 0..31
    int h  = tid & 3;                    // head / quarter

    const float4* pa = reinterpret_cast<const float4*>(g_parta);
    const float*  pl = g_partl;
    int pbase = (token0 + tl) * HH + h;

    // 8 + 8 independent loads, all issued before any arithmetic
    float4 t0 = pa[pbase + 0*PSTRIDE], t1 = pa[pbase + 1*PSTRIDE];
    float4 t2 = pa[pbase + 2*PSTRIDE], t3 = pa[pbase + 3*PSTRIDE];
    float4 t4 = pa[pbase + 4*PSTRIDE], t5 = pa[pbase + 5*PSTRIDE];
    float4 t6 = pa[pbase + 6*PSTRIDE], t7 = pa[pbase + 7*PSTRIDE];
    float l0 = pl[pbase + 0*PSTRIDE], l1 = pl[pbase + 1*PSTRIDE];
    float l2 = pl[pbase + 2*PSTRIDE], l3 = pl[pbase + 3*PSTRIDE];
    float l4 = pl[pbase + 4*PSTRIDE], l5 = pl[pbase + 5*PSTRIDE];
    float l6 = pl[pbase + 6*PSTRIDE], l7 = pl[pbase + 7*PSTRIDE];

    // tree sums
    t0.x += t1.x; t0.y += t1.y; t0.z += t1.z; t0.w += t1.w;
    t2.x += t3.x; t2.y += t3.y; t2.z += t3.z; t2.w += t3.w;
    t4.x += t5.x; t4.y += t5.y; t4.z += t5.z; t4.w += t5.w;
    t6.x += t7.x; t6.y += t7.y; t6.z += t7.z; t6.w += t7.w;
    t0.x += t2.x; t0.y += t2.y; t0.z += t2.z; t0.w += t2.w;
    t4.x += t6.x; t4.y += t6.y; t4.z += t6.z; t4.w += t6.w;
    t0.x += t4.x; t0.y += t4.y; t0.z += t4.z; t0.w += t4.w;
    float l = ((l0 + l1) + (l2 + l3)) + ((l4 + l5) + (l6 + l7));

    float inv = 1.0f / l;
    float* arow = att + tl * ATT_PITCH + h * DK;
    arow[0] = t0.x * inv; arow[1] = t0.y * inv;
    arow[2] = t0.z * inv; arow[3] = t0.w * inv;
    __syncthreads();

    const float* ar = att + tl * ATT_PITCH;
    float r[4] = {0.f, 0.f, 0.f, 0.f};
    #pragma unroll
    for (int d = 0; d < 4; d++) {
        int o = h * 4 + d;
        #pragma unroll
        for (int e = 0; e < EE; e++)
            r[d] = fmaf(ar[e], wc[o * EE + e], r[d]);
    }
    reinterpret_cast<float4*>(out + (token0 + tl) * EE)[h] =
        make_float4(r[0], r[1], r[2], r[3]);
}

// ---------------------------------------------------------------------------
extern "C" void kernel_launch(void* const* d_in, const int* in_sizes, int n_in,
                              void* d_out, int out_size) {
    const float* x     = (const float*)d_in[0];
    const float* theta = (const float*)d_in[1];
    const float* Wk    = (const float*)d_in[2];
    const float* Wv    = (const float*)d_in[3];
    const float* Wc    = (const float*)d_in[4];
    float* out = (float*)d_out;

    attn_kernel<<<dim3(SS / QBLK, NBH, KSPLIT), THREADS>>>(x, theta, Wk, Wv);
    epi_kernel<<<(BB * SS) / TPB, 128>>>(Wc, out);
}